// round 9
// baseline (speedup 1.0000x reference)
#include <cuda_runtime.h>
#include <cuda_bf16.h>
#include <cstdint>

#define HW      65536
#define NVEC    16384   // HW / 4
#define NB      32
#define NP      8
#define MASK_CH 9
#define KP_CH   23

#define SV      128           // float4 vectors per channel per stage (1/thread)
#define NSTAGE  (NVEC / SV)   // 128 stages per batch
#define MBX     8             // mask blocks per batch
#define KBX     23            // kp blocks per batch
#define GX      (MBX + KBX)   // 31
#define TOTAL_BLK (GX * NB)   // 992
#define BLOCK   128

#define KP_STAGE_BYTES (KP_CH * SV * 16)       // 46 KB
#define SMEM_BYTES     (2 * KP_STAGE_BYTES)    // 92 KB double buffer

// scratch[b][p][6] = {mask_cnt, mask_sx, mask_sy, kp_cnt, kp_sx, kp_sy}
__device__ int g_scratch[NB * NP * 6];
__device__ unsigned int g_done;

__device__ __forceinline__ void cpasync16(uint32_t dst, const void* src) {
    asm volatile("cp.async.cg.shared.global [%0], [%1], 16;" :: "r"(dst), "l"(src));
}
__device__ __forceinline__ void cpcommit() {
    asm volatile("cp.async.commit_group;");
}
template <int N> __device__ __forceinline__ void cpwait() {
    asm volatile("cp.async.wait_group %0;" :: "n"(N));
}

// Threshold + packed accumulate for part `p` given part-sum float4 `S`.
// sxsy[p] = (sx<<16)|sy ; counts byte-packed in cntA/cntB.
#define ACC(p, S, TH)                                                         \
    {                                                                         \
        int c0 = (S).x > (TH);                                                \
        int c1 = (S).y > (TH);                                                \
        int c2 = (S).z > (TH);                                                \
        int c3 = (S).w > (TH);                                                \
        int n = c0 + c1 + c2 + c3;                                            \
        sxsy[p] += ((unsigned int)(row * n) << 16)                            \
                 + (unsigned int)(n * col0 + c1 + 2 * c2 + 3 * c3);           \
        if ((p) < 4) cntA += (unsigned int)n << (8 * (p));                    \
        else         cntB += (unsigned int)n << (8 * ((p) - 4));              \
    }

// Unpack packed accumulators, warp+block reduce (128 threads), commit.
__device__ __forceinline__ void reduce_commit(int b, unsigned int* sxsy,
                                              unsigned int cntA, unsigned int cntB,
                                              int off) {
    __shared__ int sh[NP * 3];
    if (threadIdx.x < NP * 3) sh[threadIdx.x] = 0;
    __syncthreads();
#pragma unroll
    for (int p = 0; p < NP; p++) {
        int a  = (int)(((p < 4 ? cntA : cntB) >> (8 * (p & 3))) & 0xFFu);
        int s1 = (int)(sxsy[p] >> 16);
        int s2 = (int)(sxsy[p] & 0xFFFFu);
#pragma unroll
        for (int d = 16; d > 0; d >>= 1) {
            a  += __shfl_down_sync(0xffffffffu, a,  d);
            s1 += __shfl_down_sync(0xffffffffu, s1, d);
            s2 += __shfl_down_sync(0xffffffffu, s2, d);
        }
        if ((threadIdx.x & 31) == 0) {
            atomicAdd(&sh[p * 3 + 0], a);
            atomicAdd(&sh[p * 3 + 1], s1);
            atomicAdd(&sh[p * 3 + 2], s2);
        }
    }
    __syncthreads();
    if (threadIdx.x < NP * 3) {
        int p = threadIdx.x / 3;
        int j = threadIdx.x % 3;
        atomicAdd(&g_scratch[(b * NP + p) * 6 + off + j], sh[threadIdx.x]);
    }
}

__global__ void __launch_bounds__(BLOCK, 2) fused_kernel(
    const float4* __restrict__ masks, const float4* __restrict__ kp,
    float* __restrict__ out)
{
    extern __shared__ float4 sbuf[];   // [2][nch * SV]
    const int b = blockIdx.y;
    const int t = threadIdx.x;
    unsigned int sxsy[NP];
    unsigned int cntA = 0u, cntB = 0u;
#pragma unroll
    for (int p = 0; p < NP; p++) sxsy[p] = 0u;

    const bool is_mask = (blockIdx.x < MBX);
    const int nch = is_mask ? NP : KP_CH;

    // Per-path contiguous stage ranges (bytes balanced: 8ch/8blk == 23ch/23blk)
    int start, ns;
    if (is_mask) {
        start = blockIdx.x * (NSTAGE / MBX);           // 16 stages each
        ns    = NSTAGE / MBX;
    } else {
        int j = blockIdx.x - MBX;                      // 0..22; 128 = 23*5+13
        start = j * 5 + min(j, 13);
        ns    = 5 + (j < 13 ? 1 : 0);
    }

    const float4* base = is_mask
        ? masks + (size_t)b * MASK_CH * NVEC + NVEC     // skip channel 0
        : kp    + (size_t)b * KP_CH   * NVEC;

    const uint32_t smem0 = (uint32_t)__cvta_generic_to_shared(sbuf);

    // Issue one stage's cp.asyncs: every thread copies one float4 per channel.
    auto issue = [&](int stage, int bufsel) {
        uint32_t dst = smem0 + (uint32_t)bufsel * KP_STAGE_BYTES + t * 16;
        const float4* src = base + stage * SV + t;
        for (int ch = 0; ch < nch; ch++) {
            cpasync16(dst, (const void*)src);
            dst += SV * 16;
            src += NVEC;
        }
        cpcommit();
    };

    // Prologue
    issue(start, 0);

    for (int s = 0; s < ns; s++) {
        if (s + 1 < ns) { issue(start + s + 1, (s + 1) & 1); cpwait<1>(); }
        else            { cpwait<0>(); }
        __syncthreads();

        const float4* buf = sbuf + (size_t)(s & 1) * (KP_STAGE_BYTES / 16);
        const int i    = (start + s) * SV + t;   // vector index in this batch
        const int pix  = i << 2;
        const int row  = pix >> 8;
        const int col0 = pix & 255;

        if (is_mask) {
#pragma unroll
            for (int p = 0; p < NP; p++) {
                float4 v = buf[p * SV + t];
                ACC(p, v, 0.5f)
            }
        } else {
            // Sum member joints in ascending-k order (matches reference einsum),
            // thresholding each part the moment its last joint is added.
            float4 v, s0, s1v, s2, s3, s4, s5, s6, s7;
#define LDV(k) v = buf[(k) * SV + t]
#define ADD4(S) { (S).x += v.x; (S).y += v.y; (S).z += v.z; (S).w += v.w; }
            LDV(0);  s0 = v;
            LDV(1);  ADD4(s0)
            LDV(2);  ADD4(s0)
            LDV(3);  ADD4(s0)
            LDV(4);  ADD4(s0)  ACC(0, s0, 0.3f)            // p0: {0,1,2,3,4}
            LDV(5);  s1v = v; s2 = v;
            LDV(6);  ADD4(s1v) s3 = v;
            LDV(7);  ADD4(s2)
            LDV(8);  ADD4(s3)
            LDV(9);  ADD4(s2)  ACC(2, s2, 0.3f)            // p2: {5,7,9}
            LDV(10); ADD4(s3)  ACC(3, s3, 0.3f)            // p3: {6,8,10}
            LDV(11); ADD4(s1v) s4 = v;
            LDV(12); ADD4(s1v) s5 = v; ACC(1, s1v, 0.3f)   // p1: {5,6,11,12}
            LDV(13); ADD4(s4)
            LDV(14); ADD4(s5)
            LDV(15); ADD4(s4)  s6 = v; ACC(4, s4, 0.3f)    // p4: {11,13,15}
            LDV(16); ADD4(s5)  s7 = v; ACC(5, s5, 0.3f)    // p5: {12,14,16}
            LDV(17); ADD4(s6)
            LDV(18); ADD4(s6)
            LDV(19); ADD4(s6)  ACC(6, s6, 0.3f)            // p6: {15,17,18,19}
            LDV(20); ADD4(s7)
            LDV(21); ADD4(s7)
            LDV(22); ADD4(s7)  ACC(7, s7, 0.3f)            // p7: {16,20,21,22}
#undef LDV
#undef ADD4
        }
        __syncthreads();   // buffer reusable before next issue overwrites it
    }

    reduce_commit(b, sxsy, cntA, cntB, is_mask ? 0 : 3);

    // ---- Last-block finalize (threadfence-reduction pattern) ----
    __shared__ unsigned int s_last;
    __threadfence();
    __syncthreads();
    if (t == 0) {
        unsigned int ticket = atomicAdd(&g_done, 1u);
        s_last = (ticket == TOTAL_BLK - 1) ? 1u : 0u;
    }
    __syncthreads();
    if (s_last == 0u) return;

    __threadfence();   // acquire side

    // 128 threads cover 256 (batch, part) entries in two passes.
    float num = 0.f, vc = 0.f;
#pragma unroll
    for (int pass = 0; pass < 2; pass++) {
        int e = t + pass * BLOCK;
        volatile int* s = &g_scratch[e * 6];
        int mc  = s[0], msx = s[1], msy = s[2];
        int kc  = s[3], ksx = s[4], ksy = s[5];

        float mdiv = fmaxf((float)mc, 1.f);
        float mmx = (float)msx / mdiv;
        float mmy = (float)msy / mdiv;
        float mcx = (mc > 0 && mmx > 0.f) ? mmx : 0.f;
        float mcy = (mc > 0 && mmy > 0.f) ? mmy : 0.f;

        float kdiv = fmaxf((float)kc, 1.f);
        float kmx = (float)ksx / kdiv;
        float kmy = (float)ksy / kdiv;
        float kcx = (kc > 0 && kmx > 0.f) ? kmx : 0.f;
        float kcy = (kc > 0 && kmy > 0.f) ? kmy : 0.f;

        bool code = (kcx == 0.f) || (kcy == 0.f) || (mcx == 0.f) || (mcy == 0.f);
        if (!code) {
            float dx = mcx - kcx;
            float dy = mcy - kcy;
            num += dx * dx + dy * dy;
            vc  += 1.f;
        }
    }

    __shared__ float shn[4], shc[4];
#pragma unroll
    for (int d = 16; d > 0; d >>= 1) {
        num += __shfl_down_sync(0xffffffffu, num, d);
        vc  += __shfl_down_sync(0xffffffffu, vc,  d);
    }
    if ((t & 31) == 0) { shn[t >> 5] = num; shc[t >> 5] = vc; }
    __syncthreads();
    if (t == 0) {
        float n = 0.f, c = 0.f;
#pragma unroll
        for (int w = 0; w < 4; w++) { n += shn[w]; c += shc[w]; }
        out[0] = 1e-5f * (n / (c * 2.0f));
    }

    // Reset state for the next graph replay (statics start at 0 -> deterministic).
    __syncthreads();
    for (int j = t; j < NB * NP * 6; j += BLOCK) g_scratch[j] = 0;
    if (t == 0) g_done = 0u;
}

extern "C" void kernel_launch(void* const* d_in, const int* in_sizes, int n_in,
                              void* d_out, int out_size) {
    // Identify inputs by element count (robust to metadata ordering).
    const int MASK_ELEMS = NB * MASK_CH * HW;  // 18,874,368
    const float* masks;
    const float* kp;
    if (in_sizes[0] == MASK_ELEMS) {
        masks = (const float*)d_in[0];
        kp    = (const float*)d_in[1];
    } else {
        masks = (const float*)d_in[1];
        kp    = (const float*)d_in[0];
    }

    static bool attr_set = false;
    if (!attr_set) {
        cudaFuncSetAttribute(fused_kernel,
                             cudaFuncAttributeMaxDynamicSharedMemorySize,
                             SMEM_BYTES);
        attr_set = true;
    }

    fused_kernel<<<dim3(GX, NB), BLOCK, SMEM_BYTES>>>((const float4*)masks,
                                                      (const float4*)kp,
                                                      (float*)d_out);
}

// round 10
// speedup vs baseline: 1.2485x; 1.2485x over previous
#include <cuda_runtime.h>
#include <cuda_bf16.h>

#define HW      65536
#define NVEC    16384   // HW / 4
#define NB      32
#define NP      8
#define MASK_CH 9
#define KP_CH   23

#define BLOCK   128
#define MBX     10            // mask blocks per batch
#define KBX     27            // kp blocks per batch
#define GX      (MBX + KBX)   // 37
#define TOTAL_BLK (GX * NB)   // 1184 = exactly one wave at 8 CTAs/SM on 148 SMs

// scratch[b][p][6] = {mask_cnt, mask_sx, mask_sy, kp_cnt, kp_sx, kp_sy}
__device__ int g_scratch[NB * NP * 6];
__device__ unsigned int g_done;

// Threshold + packed accumulate for part `p` given part-sum float4 `S`.
// sxsy[p] = (sx<<16)|sy ; counts byte-packed in cntA/cntB.
#define ACC(p, S, TH)                                                         \
    {                                                                         \
        int c0 = (S).x > (TH);                                                \
        int c1 = (S).y > (TH);                                                \
        int c2 = (S).z > (TH);                                                \
        int c3 = (S).w > (TH);                                                \
        int n = c0 + c1 + c2 + c3;                                            \
        sxsy[p] += ((unsigned int)(row * n) << 16)                            \
                 + (unsigned int)(n * col0 + c1 + 2 * c2 + 3 * c3);           \
        if ((p) < 4) cntA += (unsigned int)n << (8 * (p));                    \
        else         cntB += (unsigned int)n << (8 * ((p) - 4));              \
    }

// Masks: L2-resident set (default policy keeps them in L2 across graph replays).
__device__ __forceinline__ void mask_body(const float4* __restrict__ base, int i,
                                          unsigned int* sxsy,
                                          unsigned int& cntA, unsigned int& cntB) {
    const int pix  = i << 2;
    const int row  = pix >> 8;
    const int col0 = pix & 255;
#pragma unroll
    for (int p = 0; p < NP; p++) {
        float4 v = __ldg(base + p * NVEC + i);
        ACC(p, v, 0.5f)
    }
}

// Keypoints: channels 0-4 L2-resident (__ldg), channels 5-22 streaming
// (__ldcs, evict-first so they don't sweep the resident set out of L2).
// Each channel read once, fanned into member parts; each part thresholded as
// soon as its last joint (ascending k, matching the reference einsum) is added.
__device__ __forceinline__ void kp_body(const float4* __restrict__ base, int i,
                                        unsigned int* sxsy,
                                        unsigned int& cntA, unsigned int& cntB) {
    const int pix  = i << 2;
    const int row  = pix >> 8;
    const int col0 = pix & 255;
    float4 v, s0, s1, s2, s3, s4, s5, s6, s7;
#define LDR(k) v = __ldg(base + (k) * NVEC + i)     // resident channels
#define LDS_(k) v = __ldcs(base + (k) * NVEC + i)   // streaming channels
#define ADD4(S) { (S).x += v.x; (S).y += v.y; (S).z += v.z; (S).w += v.w; }
    LDR(0);  s0 = v;
    LDR(1);  ADD4(s0)
    LDR(2);  ADD4(s0)
    LDR(3);  ADD4(s0)
    LDR(4);  ADD4(s0)  ACC(0, s0, 0.3f)          // p0: {0,1,2,3,4}
    LDS_(5);  s1 = v; s2 = v;
    LDS_(6);  ADD4(s1)  s3 = v;
    LDS_(7);  ADD4(s2)
    LDS_(8);  ADD4(s3)
    LDS_(9);  ADD4(s2)  ACC(2, s2, 0.3f)         // p2: {5,7,9}
    LDS_(10); ADD4(s3)  ACC(3, s3, 0.3f)         // p3: {6,8,10}
    LDS_(11); ADD4(s1)  s4 = v;
    LDS_(12); ADD4(s1)  s5 = v; ACC(1, s1, 0.3f) // p1: {5,6,11,12}
    LDS_(13); ADD4(s4)
    LDS_(14); ADD4(s5)
    LDS_(15); ADD4(s4)  s6 = v; ACC(4, s4, 0.3f) // p4: {11,13,15}
    LDS_(16); ADD4(s5)  s7 = v; ACC(5, s5, 0.3f) // p5: {12,14,16}
    LDS_(17); ADD4(s6)
    LDS_(18); ADD4(s6)
    LDS_(19); ADD4(s6)  ACC(6, s6, 0.3f)         // p6: {15,17,18,19}
    LDS_(20); ADD4(s7)
    LDS_(21); ADD4(s7)
    LDS_(22); ADD4(s7)  ACC(7, s7, 0.3f)         // p7: {16,20,21,22}
#undef LDR
#undef LDS_
#undef ADD4
}

// Unpack packed accumulators, warp+block reduce (128 threads), commit.
__device__ __forceinline__ void reduce_commit(int b, unsigned int* sxsy,
                                              unsigned int cntA, unsigned int cntB,
                                              int off) {
    __shared__ int sh[NP * 3];
    if (threadIdx.x < NP * 3) sh[threadIdx.x] = 0;
    __syncthreads();
#pragma unroll
    for (int p = 0; p < NP; p++) {
        int a  = (int)(((p < 4 ? cntA : cntB) >> (8 * (p & 3))) & 0xFFu);
        int s1 = (int)(sxsy[p] >> 16);
        int s2 = (int)(sxsy[p] & 0xFFFFu);
#pragma unroll
        for (int d = 16; d > 0; d >>= 1) {
            a  += __shfl_down_sync(0xffffffffu, a,  d);
            s1 += __shfl_down_sync(0xffffffffu, s1, d);
            s2 += __shfl_down_sync(0xffffffffu, s2, d);
        }
        if ((threadIdx.x & 31) == 0) {
            atomicAdd(&sh[p * 3 + 0], a);
            atomicAdd(&sh[p * 3 + 1], s1);
            atomicAdd(&sh[p * 3 + 2], s2);
        }
    }
    __syncthreads();
    if (threadIdx.x < NP * 3) {
        int p = threadIdx.x / 3;
        int j = threadIdx.x % 3;
        atomicAdd(&g_scratch[(b * NP + p) * 6 + off + j], sh[threadIdx.x]);
    }
}

__global__ void __launch_bounds__(BLOCK, 8) fused_kernel(
    const float4* __restrict__ masks, const float4* __restrict__ kp,
    float* __restrict__ out)
{
    const int b = blockIdx.y;
    const int t = threadIdx.x;
    unsigned int sxsy[NP];
    unsigned int cntA = 0u, cntB = 0u;
#pragma unroll
    for (int p = 0; p < NP; p++) sxsy[p] = 0u;

    if (blockIdx.x < MBX) {
        // ---- Mask centroid stats: channels 1..8, threshold 0.5 ----
        const float4* base = masks + (size_t)b * MASK_CH * NVEC + NVEC;  // skip ch0
        const int stride = MBX * BLOCK;
        for (int i = blockIdx.x * BLOCK + t; i < NVEC; i += 2 * stride) {
            mask_body(base, i, sxsy, cntA, cntB);   // two independent chains:
            int i2 = i + stride;                     // ptxas batches their loads
            if (i2 < NVEC) mask_body(base, i2, sxsy, cntA, cntB);
        }
        reduce_commit(b, sxsy, cntA, cntB, 0);
    } else {
        // ---- Keypoint part-heatmap stats: threshold 0.3 ----
        const float4* base = kp + (size_t)b * KP_CH * NVEC;
        const int bx = blockIdx.x - MBX;
        const int stride = KBX * BLOCK;
        for (int i = bx * BLOCK + t; i < NVEC; i += 2 * stride) {
            kp_body(base, i, sxsy, cntA, cntB);
            int i2 = i + stride;
            if (i2 < NVEC) kp_body(base, i2, sxsy, cntA, cntB);
        }
        reduce_commit(b, sxsy, cntA, cntB, 3);
    }

    // ---- Last-block finalize (threadfence-reduction pattern) ----
    __shared__ unsigned int s_last;
    __threadfence();
    __syncthreads();
    if (t == 0) {
        unsigned int ticket = atomicAdd(&g_done, 1u);
        s_last = (ticket == TOTAL_BLK - 1) ? 1u : 0u;
    }
    __syncthreads();
    if (s_last == 0u) return;

    __threadfence();   // acquire side

    // 128 threads cover 256 (batch, part) entries in two passes.
    float num = 0.f, vc = 0.f;
#pragma unroll
    for (int pass = 0; pass < 2; pass++) {
        int e = t + pass * BLOCK;
        volatile int* s = &g_scratch[e * 6];
        int mc  = s[0], msx = s[1], msy = s[2];
        int kc  = s[3], ksx = s[4], ksy = s[5];

        float mdiv = fmaxf((float)mc, 1.f);
        float mmx = (float)msx / mdiv;
        float mmy = (float)msy / mdiv;
        float mcx = (mc > 0 && mmx > 0.f) ? mmx : 0.f;
        float mcy = (mc > 0 && mmy > 0.f) ? mmy : 0.f;

        float kdiv = fmaxf((float)kc, 1.f);
        float kmx = (float)ksx / kdiv;
        float kmy = (float)ksy / kdiv;
        float kcx = (kc > 0 && kmx > 0.f) ? kmx : 0.f;
        float kcy = (kc > 0 && kmy > 0.f) ? kmy : 0.f;

        bool code = (kcx == 0.f) || (kcy == 0.f) || (mcx == 0.f) || (mcy == 0.f);
        if (!code) {
            float dx = mcx - kcx;
            float dy = mcy - kcy;
            num += dx * dx + dy * dy;
            vc  += 1.f;
        }
    }

    __shared__ float shn[4], shc[4];
#pragma unroll
    for (int d = 16; d > 0; d >>= 1) {
        num += __shfl_down_sync(0xffffffffu, num, d);
        vc  += __shfl_down_sync(0xffffffffu, vc,  d);
    }
    if ((t & 31) == 0) { shn[t >> 5] = num; shc[t >> 5] = vc; }
    __syncthreads();
    if (t == 0) {
        float n = 0.f, c = 0.f;
#pragma unroll
        for (int w = 0; w < 4; w++) { n += shn[w]; c += shc[w]; }
        out[0] = 1e-5f * (n / (c * 2.0f));
    }

    // Reset state for the next graph replay (statics start at 0 -> deterministic).
    __syncthreads();
    for (int j = t; j < NB * NP * 6; j += BLOCK) g_scratch[j] = 0;
    if (t == 0) g_done = 0u;
}

extern "C" void kernel_launch(void* const* d_in, const int* in_sizes, int n_in,
                              void* d_out, int out_size) {
    // Identify inputs by element count (robust to metadata ordering).
    const int MASK_ELEMS = NB * MASK_CH * HW;  // 18,874,368
    const float* masks;
    const float* kp;
    if (in_sizes[0] == MASK_ELEMS) {
        masks = (const float*)d_in[0];
        kp    = (const float*)d_in[1];
    } else {
        masks = (const float*)d_in[1];
        kp    = (const float*)d_in[0];
    }

    fused_kernel<<<dim3(GX, NB), BLOCK>>>((const float4*)masks,
                                          (const float4*)kp,
                                          (float*)d_out);
}